// round 1
// baseline (speedup 1.0000x reference)
#include <cuda_runtime.h>

// ---------------------------------------------------------------------------
// ManifoldHyperConnection fused kernel, GB300 (sm_103a)
//
// Math (per token, D = n*C = 4096, n = 4, C = 1024):
//   rms   = sqrt(mean(x^2) + 1e-6)
//   d_k   = (1/rms) * sum_j x[j] * (alpha_k * norm_w[j] * W_k[j])   (24 rows)
//   H_pre = sigmoid(d_0..3  + b_pre)
//   H_post= 2*sigmoid(d_4..7 + b_post)
//   M     = d_8..23 reshaped (4,4) + b_res ; S = 0.5(M - M^T)
//   Q     = (I - S)^{-1} (I + S)            (Cayley, 4x4 Gauss-Jordan)
//   G[m,n]= Q[m,n] + H_post[m]*H_pre[n]     (folds y, o, r into one 4x4)
//   out[m,c] = sum_n G[m,n] * x[n,c]
//
// Kernel 1 (prep): fold alpha_* and norm_w into Wq[jb][k][4] (k padded to 32).
// Kernel 2 (main): 512 blocks x 256 thr, 32 tokens/block.
//   Phase 1: stream x in 4 chunks of 1024 ch through smem; lane=k weight row,
//            x broadcast via LDS.128; packed f32x2 FMA accumulators.
//            Sum-of-squares via shfl reduce during chunk load (deterministic).
//   Phase 2: reduce partials, sigmoids + Cayley + fold -> G per token.
//   Phase 3: re-read x (L2-hot), apply G, write out (packed FMA).
// ---------------------------------------------------------------------------

typedef unsigned long long u64;

__device__ __forceinline__ u64 fma2(u64 a, u64 b, u64 c) {
    u64 d;
    asm("fma.rn.f32x2 %0, %1, %2, %3;" : "=l"(d) : "l"(a), "l"(b), "l"(c));
    return d;
}
__device__ __forceinline__ u64 pk2(float lo, float hi) {
    u64 r;
    asm("mov.b64 %0, {%1, %2};" : "=l"(r) : "f"(lo), "f"(hi));
    return r;
}
__device__ __forceinline__ void upk2(u64 v, float& lo, float& hi) {
    asm("mov.b64 {%0, %1}, %2;" : "=f"(lo), "=f"(hi) : "l"(v));
}

static __device__ float g_Wq[1024 * 32 * 4];  // [jb][k][u], 512 KB scratch

// ---------------------------------------------------------------------------
// prep: Wq[jb*128 + k*4 + u] = alpha_k * norm_w[j] * W_k[j],  j = 4*jb + u
//       rows k: 0-3 = W_pre (alpha_pre), 4-7 = W_post (alpha_post),
//               8-23 = W_res (alpha_res), 24-31 = 0 (padding lanes)
// ---------------------------------------------------------------------------
__global__ void mhc_prep_kernel(const float* __restrict__ norm_w,
                                const float* __restrict__ W_pre,
                                const float* __restrict__ W_post,
                                const float* __restrict__ W_res,
                                const float* __restrict__ a_pre,
                                const float* __restrict__ a_post,
                                const float* __restrict__ a_res) {
    int idx = blockIdx.x * 256 + threadIdx.x;
    if (idx >= 1024 * 32 * 4) return;
    int jb  = idx >> 7;
    int rem = idx & 127;
    int k   = rem >> 2;
    int u   = rem & 3;
    int j   = jb * 4 + u;
    float v = 0.0f;
    if (k < 4)        v = a_pre[0]  * W_pre[k * 4096 + j];
    else if (k < 8)   v = a_post[0] * W_post[(k - 4) * 4096 + j];
    else if (k < 24)  v = a_res[0]  * W_res[(k - 8) * 4096 + j];
    g_Wq[idx] = v * norm_w[j];
}

// smem layout (bytes)
#define SMEM_SX    0          // float sx[32][1024]          131072
#define SMEM_PART  131072     // float part[8][32][32]        32768
#define SMEM_SSQP  163840     // float ssqp[8][32]             1024
#define SMEM_SSQR  164864     // float ssqr[32]                 128
#define SMEM_DOTS  164992     // float dots[32][24]            3072
#define SMEM_SG    168064     // float sG[32][16]              2048
#define SMEM_TOTAL 170112

__global__ void __launch_bounds__(256, 1)
mhc_main_kernel(const float* __restrict__ x,
                const float* __restrict__ b_pre,
                const float* __restrict__ b_post,
                const float* __restrict__ b_res,
                float* __restrict__ out) {
    extern __shared__ char smem[];
    float4*            sx4 = (float4*)(smem + SMEM_SX);
    const ulonglong2*  sxu = (const ulonglong2*)(smem + SMEM_SX);
    float*            part = (float*)(smem + SMEM_PART);
    float*            ssqp = (float*)(smem + SMEM_SSQP);
    float*            ssqr = (float*)(smem + SMEM_SSQR);
    float*            dots = (float*)(smem + SMEM_DOTS);
    float*            sG   = (float*)(smem + SMEM_SG);

    const int tid  = threadIdx.x;
    const int g    = tid >> 5;   // warp id 0..7 (j-subgroup)
    const int lane = tid & 31;   // weight row k (0..23 used)
    const int tok0 = blockIdx.x * 32;

    const float4*     x4g = (const float4*)x;
    const ulonglong2* xg2 = (const ulonglong2*)x;
    const ulonglong2* wq2 = (const ulonglong2*)g_Wq;

    u64 acc[32];
#pragma unroll
    for (int t = 0; t < 32; t++) acc[t] = 0ull;
    float ssql = 0.0f;  // lane t collects warp-partial sumsq for token t

    // ------------------ Phase 1: dots over 4 chunks of 1024 channels --------
    for (int cc = 0; cc < 4; cc++) {
        __syncthreads();  // previous chunk's compute done before overwrite
        // load chunk: iteration i loads token i's 1024-ch slice (coalesced)
        for (int i = 0; i < 32; i++) {
            float4 v = x4g[(size_t)(tok0 + i) * 1024 + cc * 256 + tid];
            sx4[i * 256 + tid] = v;
            float s = fmaf(v.x, v.x, fmaf(v.y, v.y, fmaf(v.z, v.z, v.w * v.w)));
            s += __shfl_xor_sync(0xffffffffu, s, 16);
            s += __shfl_xor_sync(0xffffffffu, s, 8);
            s += __shfl_xor_sync(0xffffffffu, s, 4);
            s += __shfl_xor_sync(0xffffffffu, s, 2);
            s += __shfl_xor_sync(0xffffffffu, s, 1);
            if (lane == i) ssql += s;
        }
        __syncthreads();

        // compute: warp g covers j4 in [g*32, g*32+32) of this chunk
        const int jl0 = g * 32;
        ulonglong2 wnext = wq2[(size_t)((cc << 8) + jl0) * 32 + lane];
#pragma unroll 1
        for (int m = 0; m < 32; m++) {
            ulonglong2 w = wnext;
            if (m < 31)
                wnext = wq2[(size_t)((cc << 8) + jl0 + m + 1) * 32 + lane];
            const int jl = jl0 + m;
#pragma unroll
            for (int t = 0; t < 32; t++) {
                ulonglong2 xv = sxu[t * 256 + jl];  // LDS.128 broadcast
                acc[t] = fma2(w.x, xv.x, acc[t]);
                acc[t] = fma2(w.y, xv.y, acc[t]);
            }
        }
    }

    // ------------------ Phase 2: reductions, sigmoids, Cayley, fold ---------
#pragma unroll
    for (int t = 0; t < 32; t++) {
        float lo, hi;
        upk2(acc[t], lo, hi);
        part[(g * 32 + t) * 32 + lane] = lo + hi;  // part[g][t][k]
    }
    ssqp[g * 32 + lane] = ssql;
    __syncthreads();

    for (int idx = tid; idx < 32 * 24; idx += 256) {
        int t = idx / 24;
        int k = idx - t * 24;
        float s = 0.0f;
#pragma unroll
        for (int gg = 0; gg < 8; gg++) s += part[(gg * 32 + t) * 32 + k];
        dots[t * 24 + k] = s;
    }
    if (tid < 32) {
        float s = 0.0f;
#pragma unroll
        for (int gg = 0; gg < 8; gg++) s += ssqp[gg * 32 + tid];
        ssqr[tid] = s;
    }
    __syncthreads();

    if (tid < 32) {
        const int t = tid;
        float rinv = rsqrtf(ssqr[t] * (1.0f / 4096.0f) + 1e-6f);
        float d[24];
#pragma unroll
        for (int k = 0; k < 24; k++) d[k] = dots[t * 24 + k] * rinv;

        float Hpre[4], Hpost[4];
#pragma unroll
        for (int i = 0; i < 4; i++) {
            Hpre[i]  = 1.0f / (1.0f + expf(-(d[i]     + b_pre[i])));
            Hpost[i] = 2.0f / (1.0f + expf(-(d[4 + i] + b_post[i])));
        }
        // Cayley: A = I - S, Bq = I + S, S = 0.5 (M - M^T)
        float A[4][4], Bq[4][4];
#pragma unroll
        for (int a = 0; a < 4; a++)
#pragma unroll
            for (int b = 0; b < 4; b++) {
                float Mab = d[8 + a * 4 + b] + b_res[a * 4 + b];
                float Mba = d[8 + b * 4 + a] + b_res[b * 4 + a];
                float S   = 0.5f * (Mab - Mba);
                float id  = (a == b) ? 1.0f : 0.0f;
                A[a][b]  = id - S;
                Bq[a][b] = id + S;
            }
        // Gauss-Jordan (I - S is PD symmetric-part, no pivoting needed)
#pragma unroll
        for (int r = 0; r < 4; r++) {
            float inv = 1.0f / A[r][r];
#pragma unroll
            for (int c = 0; c < 4; c++) { A[r][c] *= inv; Bq[r][c] *= inv; }
#pragma unroll
            for (int rr = 0; rr < 4; rr++) {
                if (rr == r) continue;
                float f = A[rr][r];
#pragma unroll
                for (int c = 0; c < 4; c++) {
                    A[rr][c]  -= f * A[r][c];
                    Bq[rr][c] -= f * Bq[r][c];
                }
            }
        }
#pragma unroll
        for (int m = 0; m < 4; m++)
#pragma unroll
            for (int n = 0; n < 4; n++)
                sG[t * 16 + m * 4 + n] = Bq[m][n] + Hpost[m] * Hpre[n];
    }
    __syncthreads();

    // ------------------ Phase 3: out = G @ x (per token) --------------------
    ulonglong2* og2 = (ulonglong2*)out;
    for (int it = 0; it < 32; it++) {
        u64 g2a[16];
#pragma unroll
        for (int q = 0; q < 16; q++) {
            float gv = sG[it * 16 + q];
            g2a[q] = pk2(gv, gv);
        }
        u64 xl[4], xh[4];
#pragma unroll
        for (int n = 0; n < 4; n++) {
            ulonglong2 v = xg2[(size_t)(tok0 + it) * 1024 + n * 256 + tid];
            xl[n] = v.x;
            xh[n] = v.y;
        }
#pragma unroll
        for (int m = 0; m < 4; m++) {
            u64 al = 0ull, ah = 0ull;
#pragma unroll
            for (int n = 0; n < 4; n++) {
                al = fma2(g2a[m * 4 + n], xl[n], al);
                ah = fma2(g2a[m * 4 + n], xh[n], ah);
            }
            ulonglong2 o;
            o.x = al;
            o.y = ah;
            og2[(size_t)(tok0 + it) * 1024 + m * 256 + tid] = o;
        }
    }
}

extern "C" void kernel_launch(void* const* d_in, const int* in_sizes, int n_in,
                              void* d_out, int out_size) {
    const float* x      = (const float*)d_in[0];
    const float* norm_w = (const float*)d_in[1];
    const float* W_pre  = (const float*)d_in[2];
    const float* W_post = (const float*)d_in[3];
    const float* W_res  = (const float*)d_in[4];
    const float* b_pre  = (const float*)d_in[5];
    const float* b_post = (const float*)d_in[6];
    const float* b_res  = (const float*)d_in[7];
    const float* a_pre  = (const float*)d_in[8];
    const float* a_post = (const float*)d_in[9];
    const float* a_res  = (const float*)d_in[10];
    float* out = (float*)d_out;

    const int BL   = in_sizes[0] / 4096;  // 16384 tokens
    const int nblk = BL / 32;             // 512 blocks

    cudaFuncSetAttribute(mhc_main_kernel,
                         cudaFuncAttributeMaxDynamicSharedMemorySize,
                         SMEM_TOTAL);

    mhc_prep_kernel<<<512, 256>>>(norm_w, W_pre, W_post, W_res,
                                  a_pre, a_post, a_res);
    mhc_main_kernel<<<nblk, 256, SMEM_TOTAL>>>(x, b_pre, b_post, b_res, out);
}

// round 2
// speedup vs baseline: 1.0006x; 1.0006x over previous
#include <cuda_runtime.h>

// ---------------------------------------------------------------------------
// ManifoldHyperConnection fused kernel, GB300 (sm_103a)
//
// Math (per token, D = n*C = 4096, n = 4, C = 1024):
//   rms   = sqrt(mean(x^2) + 1e-6)
//   d_k   = (1/rms) * sum_j x[j] * (alpha_k * norm_w[j] * W_k[j])   (24 rows)
//   H_pre = sigmoid(d_0..3  + b_pre)
//   H_post= 2*sigmoid(d_4..7 + b_post)
//   M     = d_8..23 reshaped (4,4) + b_res ; S = 0.5(M - M^T)
//   Q     = (I - S)^{-1} (I + S)            (Cayley, 4x4 Gauss-Jordan)
//   G[m,n]= Q[m,n] + H_post[m]*H_pre[n]     (folds y, o, r into one 4x4)
//   out[m,c] = sum_n G[m,n] * x[n,c]
//
// Kernel 1 (prep): fold alpha_* and norm_w into Wq[jb][k][4] (k padded to 32).
// Kernel 2 (main): 512 blocks x 256 thr, 32 tokens/block.
//   Phase 1: stream x in 4 chunks of 1024 ch through smem; lane=k weight row,
//            x broadcast via LDS.128; packed f32x2 FMA accumulators.
//            Sum-of-squares via shfl reduce during chunk load (deterministic).
//   Phase 2: reduce partials, sigmoids + Cayley + fold -> G per token.
//   Phase 3: re-read x (L2-hot), apply G, write out (packed FMA).
// ---------------------------------------------------------------------------

typedef unsigned long long u64;

__device__ __forceinline__ u64 fma2(u64 a, u64 b, u64 c) {
    u64 d;
    asm("fma.rn.f32x2 %0, %1, %2, %3;" : "=l"(d) : "l"(a), "l"(b), "l"(c));
    return d;
}
__device__ __forceinline__ u64 pk2(float lo, float hi) {
    u64 r;
    asm("mov.b64 %0, {%1, %2};" : "=l"(r) : "f"(lo), "f"(hi));
    return r;
}
__device__ __forceinline__ void upk2(u64 v, float& lo, float& hi) {
    asm("mov.b64 {%0, %1}, %2;" : "=f"(lo), "=f"(hi) : "l"(v));
}

static __device__ float g_Wq[1024 * 32 * 4];  // [jb][k][u], 512 KB scratch

// ---------------------------------------------------------------------------
// prep: Wq[jb*128 + k*4 + u] = alpha_k * norm_w[j] * W_k[j],  j = 4*jb + u
//       rows k: 0-3 = W_pre (alpha_pre), 4-7 = W_post (alpha_post),
//               8-23 = W_res (alpha_res), 24-31 = 0 (padding lanes)
// ---------------------------------------------------------------------------
__global__ void mhc_prep_kernel(const float* __restrict__ norm_w,
                                const float* __restrict__ W_pre,
                                const float* __restrict__ W_post,
                                const float* __restrict__ W_res,
                                const float* __restrict__ a_pre,
                                const float* __restrict__ a_post,
                                const float* __restrict__ a_res) {
    int idx = blockIdx.x * 256 + threadIdx.x;
    if (idx >= 1024 * 32 * 4) return;
    int jb  = idx >> 7;
    int rem = idx & 127;
    int k   = rem >> 2;
    int u   = rem & 3;
    int j   = jb * 4 + u;
    float v = 0.0f;
    if (k < 4)        v = a_pre[0]  * W_pre[k * 4096 + j];
    else if (k < 8)   v = a_post[0] * W_post[(k - 4) * 4096 + j];
    else if (k < 24)  v = a_res[0]  * W_res[(k - 8) * 4096 + j];
    g_Wq[idx] = v * norm_w[j];
}

// smem layout (bytes)
#define SMEM_SX    0          // float sx[32][1024]          131072
#define SMEM_PART  131072     // float part[8][32][32]        32768
#define SMEM_SSQP  163840     // float ssqp[8][32]             1024
#define SMEM_SSQR  164864     // float ssqr[32]                 128
#define SMEM_DOTS  164992     // float dots[32][24]            3072
#define SMEM_SG    168064     // float sG[32][16]              2048
#define SMEM_TOTAL 170112

__global__ void __launch_bounds__(256, 1)
mhc_main_kernel(const float* __restrict__ x,
                const float* __restrict__ b_pre,
                const float* __restrict__ b_post,
                const float* __restrict__ b_res,
                float* __restrict__ out) {
    extern __shared__ char smem[];
    float4*            sx4 = (float4*)(smem + SMEM_SX);
    const ulonglong2*  sxu = (const ulonglong2*)(smem + SMEM_SX);
    float*            part = (float*)(smem + SMEM_PART);
    float*            ssqp = (float*)(smem + SMEM_SSQP);
    float*            ssqr = (float*)(smem + SMEM_SSQR);
    float*            dots = (float*)(smem + SMEM_DOTS);
    float*            sG   = (float*)(smem + SMEM_SG);

    const int tid  = threadIdx.x;
    const int g    = tid >> 5;   // warp id 0..7 (j-subgroup)
    const int lane = tid & 31;   // weight row k (0..23 used)
    const int tok0 = blockIdx.x * 32;

    const float4*     x4g = (const float4*)x;
    const ulonglong2* xg2 = (const ulonglong2*)x;
    const ulonglong2* wq2 = (const ulonglong2*)g_Wq;

    u64 acc[32];
#pragma unroll
    for (int t = 0; t < 32; t++) acc[t] = 0ull;
    float ssql = 0.0f;  // lane t collects warp-partial sumsq for token t

    // ------------------ Phase 1: dots over 4 chunks of 1024 channels --------
    for (int cc = 0; cc < 4; cc++) {
        __syncthreads();  // previous chunk's compute done before overwrite
        // load chunk: iteration i loads token i's 1024-ch slice (coalesced)
        for (int i = 0; i < 32; i++) {
            float4 v = x4g[(size_t)(tok0 + i) * 1024 + cc * 256 + tid];
            sx4[i * 256 + tid] = v;
            float s = fmaf(v.x, v.x, fmaf(v.y, v.y, fmaf(v.z, v.z, v.w * v.w)));
            s += __shfl_xor_sync(0xffffffffu, s, 16);
            s += __shfl_xor_sync(0xffffffffu, s, 8);
            s += __shfl_xor_sync(0xffffffffu, s, 4);
            s += __shfl_xor_sync(0xffffffffu, s, 2);
            s += __shfl_xor_sync(0xffffffffu, s, 1);
            if (lane == i) ssql += s;
        }
        __syncthreads();

        // compute: warp g covers j4 in [g*32, g*32+32) of this chunk
        const int jl0 = g * 32;
        ulonglong2 wnext = wq2[(size_t)((cc << 8) + jl0) * 32 + lane];
#pragma unroll 1
        for (int m = 0; m < 32; m++) {
            ulonglong2 w = wnext;
            if (m < 31)
                wnext = wq2[(size_t)((cc << 8) + jl0 + m + 1) * 32 + lane];
            const int jl = jl0 + m;
#pragma unroll
            for (int t = 0; t < 32; t++) {
                ulonglong2 xv = sxu[t * 256 + jl];  // LDS.128 broadcast
                acc[t] = fma2(w.x, xv.x, acc[t]);
                acc[t] = fma2(w.y, xv.y, acc[t]);
            }
        }
    }

    // ------------------ Phase 2: reductions, sigmoids, Cayley, fold ---------
#pragma unroll
    for (int t = 0; t < 32; t++) {
        float lo, hi;
        upk2(acc[t], lo, hi);
        part[(g * 32 + t) * 32 + lane] = lo + hi;  // part[g][t][k]
    }
    ssqp[g * 32 + lane] = ssql;
    __syncthreads();

    for (int idx = tid; idx < 32 * 24; idx += 256) {
        int t = idx / 24;
        int k = idx - t * 24;
        float s = 0.0f;
#pragma unroll
        for (int gg = 0; gg < 8; gg++) s += part[(gg * 32 + t) * 32 + k];
        dots[t * 24 + k] = s;
    }
    if (tid < 32) {
        float s = 0.0f;
#pragma unroll
        for (int gg = 0; gg < 8; gg++) s += ssqp[gg * 32 + tid];
        ssqr[tid] = s;
    }
    __syncthreads();

    if (tid < 32) {
        const int t = tid;
        float rinv = rsqrtf(ssqr[t] * (1.0f / 4096.0f) + 1e-6f);
        float d[24];
#pragma unroll
        for (int k = 0; k < 24; k++) d[k] = dots[t * 24 + k] * rinv;

        float Hpre[4], Hpost[4];
#pragma unroll
        for (int i = 0; i < 4; i++) {
            Hpre[i]  = 1.0f / (1.0f + expf(-(d[i]     + b_pre[i])));
            Hpost[i] = 2.0f / (1.0f + expf(-(d[4 + i] + b_post[i])));
        }
        // Cayley: A = I - S, Bq = I + S, S = 0.5 (M - M^T)
        float A[4][4], Bq[4][4];
#pragma unroll
        for (int a = 0; a < 4; a++)
#pragma unroll
            for (int b = 0; b < 4; b++) {
                float Mab = d[8 + a * 4 + b] + b_res[a * 4 + b];
                float Mba = d[8 + b * 4 + a] + b_res[b * 4 + a];
                float S   = 0.5f * (Mab - Mba);
                float id  = (a == b) ? 1.0f : 0.0f;
                A[a][b]  = id - S;
                Bq[a][b] = id + S;
            }
        // Gauss-Jordan (I - S is PD symmetric-part, no pivoting needed)
#pragma unroll
        for (int r = 0; r < 4; r++) {
            float inv = 1.0f / A[r][r];
#pragma unroll
            for (int c = 0; c < 4; c++) { A[r][c] *= inv; Bq[r][c] *= inv; }
#pragma unroll
            for (int rr = 0; rr < 4; rr++) {
                if (rr == r) continue;
                float f = A[rr][r];
#pragma unroll
                for (int c = 0; c < 4; c++) {
                    A[rr][c]  -= f * A[r][c];
                    Bq[rr][c] -= f * Bq[r][c];
                }
            }
        }
#pragma unroll
        for (int m = 0; m < 4; m++)
#pragma unroll
            for (int n = 0; n < 4; n++)
                sG[t * 16 + m * 4 + n] = Bq[m][n] + Hpost[m] * Hpre[n];
    }
    __syncthreads();

    // ------------------ Phase 3: out = G @ x (per token) --------------------
    ulonglong2* og2 = (ulonglong2*)out;
    for (int it = 0; it < 32; it++) {
        u64 g2a[16];
#pragma unroll
        for (int q = 0; q < 16; q++) {
            float gv = sG[it * 16 + q];
            g2a[q] = pk2(gv, gv);
        }
        u64 xl[4], xh[4];
#pragma unroll
        for (int n = 0; n < 4; n++) {
            ulonglong2 v = xg2[(size_t)(tok0 + it) * 1024 + n * 256 + tid];
            xl[n] = v.x;
            xh[n] = v.y;
        }
#pragma unroll
        for (int m = 0; m < 4; m++) {
            u64 al = 0ull, ah = 0ull;
#pragma unroll
            for (int n = 0; n < 4; n++) {
                al = fma2(g2a[m * 4 + n], xl[n], al);
                ah = fma2(g2a[m * 4 + n], xh[n], ah);
            }
            ulonglong2 o;
            o.x = al;
            o.y = ah;
            og2[(size_t)(tok0 + it) * 1024 + m * 256 + tid] = o;
        }
    }
}

extern "C" void kernel_launch(void* const* d_in, const int* in_sizes, int n_in,
                              void* d_out, int out_size) {
    const float* x      = (const float*)d_in[0];
    const float* norm_w = (const float*)d_in[1];
    const float* W_pre  = (const float*)d_in[2];
    const float* W_post = (const float*)d_in[3];
    const float* W_res  = (const float*)d_in[4];
    const float* b_pre  = (const float*)d_in[5];
    const float* b_post = (const float*)d_in[6];
    const float* b_res  = (const float*)d_in[7];
    const float* a_pre  = (const float*)d_in[8];
    const float* a_post = (const float*)d_in[9];
    const float* a_res  = (const float*)d_in[10];
    float* out = (float*)d_out;

    const int BL   = in_sizes[0] / 4096;  // 16384 tokens
    const int nblk = BL / 32;             // 512 blocks

    cudaFuncSetAttribute(mhc_main_kernel,
                         cudaFuncAttributeMaxDynamicSharedMemorySize,
                         SMEM_TOTAL);

    mhc_prep_kernel<<<512, 256>>>(norm_w, W_pre, W_post, W_res,
                                  a_pre, a_post, a_res);
    mhc_main_kernel<<<nblk, 256, SMEM_TOTAL>>>(x, b_pre, b_post, b_res, out);
}

// round 3
// speedup vs baseline: 1.0042x; 1.0037x over previous
#include <cuda_runtime.h>

// ---------------------------------------------------------------------------
// ManifoldHyperConnection fused kernel, GB300 (sm_103a)
//
// Math (per token, D = n*C = 4096, n = 4, C = 1024):
//   rms   = sqrt(mean(x^2) + 1e-6)
//   d_k   = (1/rms) * sum_j x[j] * (alpha_k * norm_w[j] * W_k[j])   (24 rows)
//   H_pre = sigmoid(d_0..3  + b_pre)
//   H_post= 2*sigmoid(d_4..7 + b_post)
//   M     = d_8..23 reshaped (4,4) + b_res ; S = 0.5(M - M^T)
//   Q     = (I - S)^{-1} (I + S)            (Cayley, 4x4 Gauss-Jordan)
//   G[m,n]= Q[m,n] + H_post[m]*H_pre[n]     (folds y, o, r into one 4x4)
//   out[m,c] = sum_n G[m,n] * x[n,c]
//
// Kernel 1 (prep): fold alpha_* and norm_w into Wq[jb][k][4] (k padded to 32).
// Kernel 2 (main): 512 blocks x 256 thr, 32 tokens/block.
//   Phase 1: stream x in 4 chunks of 1024 ch through smem; lane=k weight row,
//            x broadcast via LDS.128; packed f32x2 FMA accumulators.
//            Sum-of-squares via shfl reduce during chunk load (deterministic).
//   Phase 2: reduce partials, sigmoids + Cayley + fold -> G per token.
//   Phase 3: re-read x (L2-hot), apply G, write out (packed FMA).
// ---------------------------------------------------------------------------

typedef unsigned long long u64;

__device__ __forceinline__ u64 fma2(u64 a, u64 b, u64 c) {
    u64 d;
    asm("fma.rn.f32x2 %0, %1, %2, %3;" : "=l"(d) : "l"(a), "l"(b), "l"(c));
    return d;
}
__device__ __forceinline__ u64 pk2(float lo, float hi) {
    u64 r;
    asm("mov.b64 %0, {%1, %2};" : "=l"(r) : "f"(lo), "f"(hi));
    return r;
}
__device__ __forceinline__ void upk2(u64 v, float& lo, float& hi) {
    asm("mov.b64 {%0, %1}, %2;" : "=f"(lo), "=f"(hi) : "l"(v));
}

static __device__ float g_Wq[1024 * 32 * 4];  // [jb][k][u], 512 KB scratch

// ---------------------------------------------------------------------------
// prep: Wq[jb*128 + k*4 + u] = alpha_k * norm_w[j] * W_k[j],  j = 4*jb + u
//       rows k: 0-3 = W_pre (alpha_pre), 4-7 = W_post (alpha_post),
//               8-23 = W_res (alpha_res), 24-31 = 0 (padding lanes)
// ---------------------------------------------------------------------------
__global__ void mhc_prep_kernel(const float* __restrict__ norm_w,
                                const float* __restrict__ W_pre,
                                const float* __restrict__ W_post,
                                const float* __restrict__ W_res,
                                const float* __restrict__ a_pre,
                                const float* __restrict__ a_post,
                                const float* __restrict__ a_res) {
    int idx = blockIdx.x * 256 + threadIdx.x;
    if (idx >= 1024 * 32 * 4) return;
    int jb  = idx >> 7;
    int rem = idx & 127;
    int k   = rem >> 2;
    int u   = rem & 3;
    int j   = jb * 4 + u;
    float v = 0.0f;
    if (k < 4)        v = a_pre[0]  * W_pre[k * 4096 + j];
    else if (k < 8)   v = a_post[0] * W_post[(k - 4) * 4096 + j];
    else if (k < 24)  v = a_res[0]  * W_res[(k - 8) * 4096 + j];
    g_Wq[idx] = v * norm_w[j];
}

// smem layout (bytes)
#define SMEM_SX    0          // float sx[32][1024]          131072
#define SMEM_PART  131072     // float part[8][32][32]        32768
#define SMEM_SSQP  163840     // float ssqp[8][32]             1024
#define SMEM_SSQR  164864     // float ssqr[32]                 128
#define SMEM_DOTS  164992     // float dots[32][24]            3072
#define SMEM_SG    168064     // float sG[32][16]              2048
#define SMEM_TOTAL 170112

__global__ void __launch_bounds__(256, 1)
mhc_main_kernel(const float* __restrict__ x,
                const float* __restrict__ b_pre,
                const float* __restrict__ b_post,
                const float* __restrict__ b_res,
                float* __restrict__ out) {
    extern __shared__ char smem[];
    float4*            sx4 = (float4*)(smem + SMEM_SX);
    const ulonglong2*  sxu = (const ulonglong2*)(smem + SMEM_SX);
    float*            part = (float*)(smem + SMEM_PART);
    float*            ssqp = (float*)(smem + SMEM_SSQP);
    float*            ssqr = (float*)(smem + SMEM_SSQR);
    float*            dots = (float*)(smem + SMEM_DOTS);
    float*            sG   = (float*)(smem + SMEM_SG);

    const int tid  = threadIdx.x;
    const int g    = tid >> 5;   // warp id 0..7 (j-subgroup)
    const int lane = tid & 31;   // weight row k (0..23 used)
    const int tok0 = blockIdx.x * 32;

    const float4*     x4g = (const float4*)x;
    const ulonglong2* xg2 = (const ulonglong2*)x;
    const ulonglong2* wq2 = (const ulonglong2*)g_Wq;

    u64 acc[32];
#pragma unroll
    for (int t = 0; t < 32; t++) acc[t] = 0ull;
    float ssql = 0.0f;  // lane t collects warp-partial sumsq for token t

    // ------------------ Phase 1: dots over 4 chunks of 1024 channels --------
    for (int cc = 0; cc < 4; cc++) {
        __syncthreads();  // previous chunk's compute done before overwrite
        // load chunk: iteration i loads token i's 1024-ch slice (coalesced)
        for (int i = 0; i < 32; i++) {
            float4 v = x4g[(size_t)(tok0 + i) * 1024 + cc * 256 + tid];
            sx4[i * 256 + tid] = v;
            float s = fmaf(v.x, v.x, fmaf(v.y, v.y, fmaf(v.z, v.z, v.w * v.w)));
            s += __shfl_xor_sync(0xffffffffu, s, 16);
            s += __shfl_xor_sync(0xffffffffu, s, 8);
            s += __shfl_xor_sync(0xffffffffu, s, 4);
            s += __shfl_xor_sync(0xffffffffu, s, 2);
            s += __shfl_xor_sync(0xffffffffu, s, 1);
            if (lane == i) ssql += s;
        }
        __syncthreads();

        // compute: warp g covers j4 in [g*32, g*32+32) of this chunk
        const int jl0 = g * 32;
        ulonglong2 wnext = wq2[(size_t)((cc << 8) + jl0) * 32 + lane];
#pragma unroll 1
        for (int m = 0; m < 32; m++) {
            ulonglong2 w = wnext;
            if (m < 31)
                wnext = wq2[(size_t)((cc << 8) + jl0 + m + 1) * 32 + lane];
            const int jl = jl0 + m;
#pragma unroll
            for (int t = 0; t < 32; t++) {
                ulonglong2 xv = sxu[t * 256 + jl];  // LDS.128 broadcast
                acc[t] = fma2(w.x, xv.x, acc[t]);
                acc[t] = fma2(w.y, xv.y, acc[t]);
            }
        }
    }

    // ------------------ Phase 2: reductions, sigmoids, Cayley, fold ---------
#pragma unroll
    for (int t = 0; t < 32; t++) {
        float lo, hi;
        upk2(acc[t], lo, hi);
        part[(g * 32 + t) * 32 + lane] = lo + hi;  // part[g][t][k]
    }
    ssqp[g * 32 + lane] = ssql;
    __syncthreads();

    for (int idx = tid; idx < 32 * 24; idx += 256) {
        int t = idx / 24;
        int k = idx - t * 24;
        float s = 0.0f;
#pragma unroll
        for (int gg = 0; gg < 8; gg++) s += part[(gg * 32 + t) * 32 + k];
        dots[t * 24 + k] = s;
    }
    if (tid < 32) {
        float s = 0.0f;
#pragma unroll
        for (int gg = 0; gg < 8; gg++) s += ssqp[gg * 32 + tid];
        ssqr[tid] = s;
    }
    __syncthreads();

    if (tid < 32) {
        const int t = tid;
        float rinv = rsqrtf(ssqr[t] * (1.0f / 4096.0f) + 1e-6f);
        float d[24];
#pragma unroll
        for (int k = 0; k < 24; k++) d[k] = dots[t * 24 + k] * rinv;

        float Hpre[4], Hpost[4];
#pragma unroll
        for (int i = 0; i < 4; i++) {
            Hpre[i]  = 1.0f / (1.0f + expf(-(d[i]     + b_pre[i])));
            Hpost[i] = 2.0f / (1.0f + expf(-(d[4 + i] + b_post[i])));
        }
        // Cayley: A = I - S, Bq = I + S, S = 0.5 (M - M^T)
        float A[4][4], Bq[4][4];
#pragma unroll
        for (int a = 0; a < 4; a++)
#pragma unroll
            for (int b = 0; b < 4; b++) {
                float Mab = d[8 + a * 4 + b] + b_res[a * 4 + b];
                float Mba = d[8 + b * 4 + a] + b_res[b * 4 + a];
                float S   = 0.5f * (Mab - Mba);
                float id  = (a == b) ? 1.0f : 0.0f;
                A[a][b]  = id - S;
                Bq[a][b] = id + S;
            }
        // Gauss-Jordan (I - S is PD symmetric-part, no pivoting needed)
#pragma unroll
        for (int r = 0; r < 4; r++) {
            float inv = 1.0f / A[r][r];
#pragma unroll
            for (int c = 0; c < 4; c++) { A[r][c] *= inv; Bq[r][c] *= inv; }
#pragma unroll
            for (int rr = 0; rr < 4; rr++) {
                if (rr == r) continue;
                float f = A[rr][r];
#pragma unroll
                for (int c = 0; c < 4; c++) {
                    A[rr][c]  -= f * A[r][c];
                    Bq[rr][c] -= f * Bq[r][c];
                }
            }
        }
#pragma unroll
        for (int m = 0; m < 4; m++)
#pragma unroll
            for (int n = 0; n < 4; n++)
                sG[t * 16 + m * 4 + n] = Bq[m][n] + Hpost[m] * Hpre[n];
    }
    __syncthreads();

    // ------------------ Phase 3: out = G @ x (per token) --------------------
    ulonglong2* og2 = (ulonglong2*)out;
    for (int it = 0; it < 32; it++) {
        u64 g2a[16];
#pragma unroll
        for (int q = 0; q < 16; q++) {
            float gv = sG[it * 16 + q];
            g2a[q] = pk2(gv, gv);
        }
        u64 xl[4], xh[4];
#pragma unroll
        for (int n = 0; n < 4; n++) {
            ulonglong2 v = xg2[(size_t)(tok0 + it) * 1024 + n * 256 + tid];
            xl[n] = v.x;
            xh[n] = v.y;
        }
#pragma unroll
        for (int m = 0; m < 4; m++) {
            u64 al = 0ull, ah = 0ull;
#pragma unroll
            for (int n = 0; n < 4; n++) {
                al = fma2(g2a[m * 4 + n], xl[n], al);
                ah = fma2(g2a[m * 4 + n], xh[n], ah);
            }
            ulonglong2 o;
            o.x = al;
            o.y = ah;
            og2[(size_t)(tok0 + it) * 1024 + m * 256 + tid] = o;
        }
    }
}

extern "C" void kernel_launch(void* const* d_in, const int* in_sizes, int n_in,
                              void* d_out, int out_size) {
    const float* x      = (const float*)d_in[0];
    const float* norm_w = (const float*)d_in[1];
    const float* W_pre  = (const float*)d_in[2];
    const float* W_post = (const float*)d_in[3];
    const float* W_res  = (const float*)d_in[4];
    const float* b_pre  = (const float*)d_in[5];
    const float* b_post = (const float*)d_in[6];
    const float* b_res  = (const float*)d_in[7];
    const float* a_pre  = (const float*)d_in[8];
    const float* a_post = (const float*)d_in[9];
    const float* a_res  = (const float*)d_in[10];
    float* out = (float*)d_out;

    const int BL   = in_sizes[0] / 4096;  // 16384 tokens
    const int nblk = BL / 32;             // 512 blocks

    cudaFuncSetAttribute(mhc_main_kernel,
                         cudaFuncAttributeMaxDynamicSharedMemorySize,
                         SMEM_TOTAL);

    mhc_prep_kernel<<<512, 256>>>(norm_w, W_pre, W_post, W_res,
                                  a_pre, a_post, a_res);
    mhc_main_kernel<<<nblk, 256, SMEM_TOTAL>>>(x, b_pre, b_post, b_res, out);
}

// round 6
// speedup vs baseline: 1.8112x; 1.8036x over previous
#include <cuda_runtime.h>
#include <cstdint>

// ---------------------------------------------------------------------------
// ManifoldHyperConnection fused kernel, GB300 (sm_103a) — round 6
//
// out[m,c] = sum_n G[m,n] * x[n,c], G folded from sigmoid/Cayley of 24 dots.
//
// Main kernel: 1024 blocks x 256 thr, 16 tokens/block, 2 CTAs/SM.
//   Phase 1: 8 chunks of 512 channels, cp.async double-buffered.
//   Phase 2: reduce partials, sigmoids + Cayley + fold -> G per token.
//   Phase 3: re-read x (L2-hot), apply G, write out (packed FMA).
//
// R5 bug fixed: global-load token stride is 1024 float4 (was 256).
// ---------------------------------------------------------------------------

typedef unsigned long long u64;

__device__ __forceinline__ u64 fma2(u64 a, u64 b, u64 c) {
    u64 d;
    asm("fma.rn.f32x2 %0, %1, %2, %3;" : "=l"(d) : "l"(a), "l"(b), "l"(c));
    return d;
}
__device__ __forceinline__ u64 pk2(float lo, float hi) {
    u64 r;
    asm("mov.b64 %0, {%1, %2};" : "=l"(r) : "f"(lo), "f"(hi));
    return r;
}
__device__ __forceinline__ void upk2(u64 v, float& lo, float& hi) {
    asm("mov.b64 {%0, %1}, %2;" : "=f"(lo), "=f"(hi) : "l"(v));
}

static __device__ float g_Wq[1024 * 32 * 4];  // [j4][k][u], 512 KB scratch

// ---------------------------------------------------------------------------
// prep: Wq[j4*128 + k*4 + u] = alpha_k * norm_w[j] * W_k[j],  j = 4*j4 + u
//       rows k: 0-3 = W_pre, 4-7 = W_post, 8-23 = W_res, 24-31 = 0 (padding)
// ---------------------------------------------------------------------------
__global__ void mhc_prep_kernel(const float* __restrict__ norm_w,
                                const float* __restrict__ W_pre,
                                const float* __restrict__ W_post,
                                const float* __restrict__ W_res,
                                const float* __restrict__ a_pre,
                                const float* __restrict__ a_post,
                                const float* __restrict__ a_res) {
    int idx = blockIdx.x * 256 + threadIdx.x;
    if (idx >= 1024 * 32 * 4) return;
    int jb  = idx >> 7;
    int rem = idx & 127;
    int k   = rem >> 2;
    int u   = rem & 3;
    int j   = jb * 4 + u;
    float v = 0.0f;
    if (k < 4)        v = a_pre[0]  * W_pre[k * 4096 + j];
    else if (k < 8)   v = a_post[0] * W_post[(k - 4) * 4096 + j];
    else if (k < 24)  v = a_res[0]  * W_res[(k - 8) * 4096 + j];
    g_Wq[idx] = v * norm_w[j];
}

// Tile/loop config
#define T         16      // tokens per block
#define NCHUNK    8       // chunks of 512 channels
#define CHUNK_F4  128     // float4 per token per chunk
#define BUF_F4    2048    // float4 per buffer (T * CHUNK_F4)
#define BUF_BYTES 32768

// smem layout (bytes)
#define SMEM_SX    0          // 2 x [16 tok][512 ch] floats      65536
#define SMEM_PART  65536      // float part[8][16][32]            16384
#define SMEM_SSQR  81920      // float ssqr[16]                      64
#define SMEM_DOTS  81984      // float dots[16][24]                1536
#define SMEM_SG    83520      // float sG[16][16]                  1024
#define SMEM_TOTAL 84544

__device__ __forceinline__ void load_chunk(uint32_t sbase, const float4* x4g,
                                           size_t tok0, int cc, int tid) {
    const int buf = cc & 1;
    const uint32_t dst0 = sbase + buf * BUF_BYTES + tid * 16;
#pragma unroll
    for (int i = 0; i < 8; i++) {
        int idx = i * 256 + tid;        // == t*128 + c4
        int t   = idx >> 7;
        int c4  = idx & 127;
        // token stride is 1024 float4 (4096 floats); chunk cc covers
        // float4 [cc*128, cc*128+128) of the token
        const float4* src = x4g + ((tok0 + t) * 1024 + cc * CHUNK_F4 + c4);
        asm volatile("cp.async.cg.shared.global [%0], [%1], 16;"
                     :: "r"(dst0 + i * 4096), "l"(src));
    }
    asm volatile("cp.async.commit_group;");
}

__global__ void __launch_bounds__(256, 2)
mhc_main_kernel(const float* __restrict__ x,
                const float* __restrict__ b_pre,
                const float* __restrict__ b_post,
                const float* __restrict__ b_res,
                float* __restrict__ out) {
    extern __shared__ char smem[];
    const float4*     sx4  = (const float4*)(smem + SMEM_SX);
    const ulonglong2* sxu  = (const ulonglong2*)(smem + SMEM_SX);
    float*            part = (float*)(smem + SMEM_PART);
    float*            ssqr = (float*)(smem + SMEM_SSQR);
    float*            dots = (float*)(smem + SMEM_DOTS);
    float*            sG   = (float*)(smem + SMEM_SG);

    const int tid  = threadIdx.x;
    const int g    = tid >> 5;   // warp id 0..7 (j-subslice)
    const int lane = tid & 31;   // weight row k (0..23 used)
    const size_t tok0 = (size_t)blockIdx.x * T;

    const float4*     x4g = (const float4*)x;
    const ulonglong2* xg2 = (const ulonglong2*)x;
    const ulonglong2* wq2 = (const ulonglong2*)g_Wq;

    const uint32_t sbase = (uint32_t)__cvta_generic_to_shared(smem);

    u64 acc[T];
#pragma unroll
    for (int t = 0; t < T; t++) acc[t] = 0ull;
    float ssql = 0.0f;  // per-thread ssq partial (token tid>>4, strided chans)

    // ------------------ Phase 1: double-buffered chunk loop -----------------
    load_chunk(sbase, x4g, tok0, 0, tid);

    for (int cc = 0; cc < NCHUNK; cc++) {
        if (cc < NCHUNK - 1) {
            load_chunk(sbase, x4g, tok0, cc + 1, tid);
            asm volatile("cp.async.wait_group 1;");
        } else {
            asm volatile("cp.async.wait_group 0;");
        }
        __syncthreads();

        const int buf = cc & 1;

        // ssq pass: thread (t = tid>>4, u = tid&15), channels strided by 16
        {
            const int tt = tid >> 4;
            const int u  = tid & 15;
            const float4* sb = sx4 + buf * BUF_F4 + tt * CHUNK_F4;
#pragma unroll
            for (int i = 0; i < 8; i++) {
                float4 v = sb[u + i * 16];
                ssql = fmaf(v.x, v.x, ssql);
                ssql = fmaf(v.y, v.y, ssql);
                ssql = fmaf(v.z, v.z, ssql);
                ssql = fmaf(v.w, v.w, ssql);
            }
        }

        // dot pass: warp g covers j4 in [cc*128 + g*16, +16)
        {
            const ulonglong2* xb = sxu + buf * BUF_F4;  // 2048 ul2 per buf
            const int bj = cc * 128 + g * 16;
#pragma unroll
            for (int m = 0; m < 16; m++) {
                ulonglong2 w = wq2[(size_t)(bj + m) * 32 + lane];
                const int jl = g * 16 + m;
#pragma unroll
                for (int t = 0; t < T; t++) {
                    ulonglong2 xv = xb[t * 128 + jl];  // LDS.128 broadcast
                    acc[t] = fma2(w.x, xv.x, acc[t]);
                    acc[t] = fma2(w.y, xv.y, acc[t]);
                }
            }
        }
        __syncthreads();  // all reads of this buffer done before reuse
    }

    // ------------------ Phase 2: reductions, sigmoids, Cayley, fold ---------
#pragma unroll
    for (int t = 0; t < T; t++) {
        float lo, hi;
        upk2(acc[t], lo, hi);
        part[(g * T + t) * 32 + lane] = lo + hi;  // part[g][t][k]
    }
    // ssq: reduce within 16-thread group (half-warp), lane0 writes
    ssql += __shfl_xor_sync(0xffffffffu, ssql, 8);
    ssql += __shfl_xor_sync(0xffffffffu, ssql, 4);
    ssql += __shfl_xor_sync(0xffffffffu, ssql, 2);
    ssql += __shfl_xor_sync(0xffffffffu, ssql, 1);
    if ((tid & 15) == 0) ssqr[tid >> 4] = ssql;
    __syncthreads();

    for (int idx = tid; idx < T * 24; idx += 256) {
        int t = idx / 24;
        int k = idx - t * 24;
        float s = 0.0f;
#pragma unroll
        for (int gg = 0; gg < 8; gg++) s += part[(gg * T + t) * 32 + k];
        dots[t * 24 + k] = s;
    }
    __syncthreads();

    if (tid < T) {
        const int t = tid;
        float rinv = rsqrtf(ssqr[t] * (1.0f / 4096.0f) + 1e-6f);
        float d[24];
#pragma unroll
        for (int k = 0; k < 24; k++) d[k] = dots[t * 24 + k] * rinv;

        float Hpre[4], Hpost[4];
#pragma unroll
        for (int i = 0; i < 4; i++) {
            Hpre[i]  = 1.0f / (1.0f + expf(-(d[i]     + b_pre[i])));
            Hpost[i] = 2.0f / (1.0f + expf(-(d[4 + i] + b_post[i])));
        }
        // Cayley: A = I - S, Bq = I + S, S = 0.5 (M - M^T)
        float A[4][4], Bq[4][4];
#pragma unroll
        for (int a = 0; a < 4; a++)
#pragma unroll
            for (int b = 0; b < 4; b++) {
                float Mab = d[8 + a * 4 + b] + b_res[a * 4 + b];
                float Mba = d[8 + b * 4 + a] + b_res[b * 4 + a];
                float S   = 0.5f * (Mab - Mba);
                float id  = (a == b) ? 1.0f : 0.0f;
                A[a][b]  = id - S;
                Bq[a][b] = id + S;
            }
#pragma unroll
        for (int r = 0; r < 4; r++) {
            float inv = 1.0f / A[r][r];
#pragma unroll
            for (int c = 0; c < 4; c++) { A[r][c] *= inv; Bq[r][c] *= inv; }
#pragma unroll
            for (int rr = 0; rr < 4; rr++) {
                if (rr == r) continue;
                float f = A[rr][r];
#pragma unroll
                for (int c = 0; c < 4; c++) {
                    A[rr][c]  -= f * A[r][c];
                    Bq[rr][c] -= f * Bq[r][c];
                }
            }
        }
#pragma unroll
        for (int m = 0; m < 4; m++)
#pragma unroll
            for (int n = 0; n < 4; n++)
                sG[t * 16 + m * 4 + n] = Bq[m][n] + Hpost[m] * Hpre[n];
    }
    __syncthreads();

    // ------------------ Phase 3: out = G @ x (per token, L2-hot x) ----------
    ulonglong2* og2 = (ulonglong2*)out;
    for (int it = 0; it < T; it++) {
        u64 g2a[16];
#pragma unroll
        for (int q = 0; q < 16; q++) {
            float gv = sG[it * 16 + q];
            g2a[q] = pk2(gv, gv);
        }
        u64 xl[4], xh[4];
#pragma unroll
        for (int n = 0; n < 4; n++) {
            ulonglong2 v = xg2[(tok0 + it) * 1024 + n * 256 + tid];
            xl[n] = v.x;
            xh[n] = v.y;
        }
#pragma unroll
        for (int m = 0; m < 4; m++) {
            u64 al = 0ull, ah = 0ull;
#pragma unroll
            for (int n = 0; n < 4; n++) {
                al = fma2(g2a[m * 4 + n], xl[n], al);
                ah = fma2(g2a[m * 4 + n], xh[n], ah);
            }
            ulonglong2 o;
            o.x = al;
            o.y = ah;
            og2[(tok0 + it) * 1024 + m * 256 + tid] = o;
        }
    }
}

extern "C" void kernel_launch(void* const* d_in, const int* in_sizes, int n_in,
                              void* d_out, int out_size) {
    const float* x      = (const float*)d_in[0];
    const float* norm_w = (const float*)d_in[1];
    const float* W_pre  = (const float*)d_in[2];
    const float* W_post = (const float*)d_in[3];
    const float* W_res  = (const float*)d_in[4];
    const float* b_pre  = (const float*)d_in[5];
    const float* b_post = (const float*)d_in[6];
    const float* b_res  = (const float*)d_in[7];
    const float* a_pre  = (const float*)d_in[8];
    const float* a_post = (const float*)d_in[9];
    const float* a_res  = (const float*)d_in[10];
    float* out = (float*)d_out;

    const int BL   = in_sizes[0] / 4096;  // 16384 tokens
    const int nblk = BL / T;              // 1024 blocks

    cudaFuncSetAttribute(mhc_main_kernel,
                         cudaFuncAttributeMaxDynamicSharedMemorySize,
                         SMEM_TOTAL);

    mhc_prep_kernel<<<512, 256>>>(norm_w, W_pre, W_post, W_res,
                                  a_pre, a_post, a_res);
    mhc_main_kernel<<<nblk, 256, SMEM_TOTAL>>>(x, b_pre, b_post, b_res, out);
}

// round 7
// speedup vs baseline: 1.8626x; 1.0284x over previous
#include <cuda_runtime.h>
#include <cstdint>

// ---------------------------------------------------------------------------
// ManifoldHyperConnection fused kernel, GB300 (sm_103a) — round 7
//
// out[m,c] = sum_n G[m,n] * x[n,c], G folded from sigmoid/Cayley of 24 dots.
//
// Main kernel: 2048 blocks x 256 thr, 8 tokens/block, 3 CTAs/SM (reg-capped).
//   Phase 1: 8 chunks of 512 channels, cp.async double-buffered.
//            lane = weight row k (24 of 32), warp g = 16-j4 slice;
//            warp g also owns token g's sum-of-squares.
//   Phase 2: reduce partials, sigmoids + Cayley + fold -> G per token.
//   Phase 3: re-read x (L2-hot), apply G, write out (packed FMA).
// ---------------------------------------------------------------------------

typedef unsigned long long u64;

__device__ __forceinline__ u64 fma2(u64 a, u64 b, u64 c) {
    u64 d;
    asm("fma.rn.f32x2 %0, %1, %2, %3;" : "=l"(d) : "l"(a), "l"(b), "l"(c));
    return d;
}
__device__ __forceinline__ u64 pk2(float lo, float hi) {
    u64 r;
    asm("mov.b64 %0, {%1, %2};" : "=l"(r) : "f"(lo), "f"(hi));
    return r;
}
__device__ __forceinline__ void upk2(u64 v, float& lo, float& hi) {
    asm("mov.b64 {%0, %1}, %2;" : "=f"(lo), "=f"(hi) : "l"(v));
}

static __device__ float g_Wq[1024 * 32 * 4];  // [j4][k][u], 512 KB scratch

// ---------------------------------------------------------------------------
// prep: Wq[j4*128 + k*4 + u] = alpha_k * norm_w[j] * W_k[j],  j = 4*j4 + u
// ---------------------------------------------------------------------------
__global__ void mhc_prep_kernel(const float* __restrict__ norm_w,
                                const float* __restrict__ W_pre,
                                const float* __restrict__ W_post,
                                const float* __restrict__ W_res,
                                const float* __restrict__ a_pre,
                                const float* __restrict__ a_post,
                                const float* __restrict__ a_res) {
    int idx = blockIdx.x * 256 + threadIdx.x;
    if (idx >= 1024 * 32 * 4) return;
    int jb  = idx >> 7;
    int rem = idx & 127;
    int k   = rem >> 2;
    int u   = rem & 3;
    int j   = jb * 4 + u;
    float v = 0.0f;
    if (k < 4)        v = a_pre[0]  * W_pre[k * 4096 + j];
    else if (k < 8)   v = a_post[0] * W_post[(k - 4) * 4096 + j];
    else if (k < 24)  v = a_res[0]  * W_res[(k - 8) * 4096 + j];
    g_Wq[idx] = v * norm_w[j];
}

// Tile/loop config
#define T         8       // tokens per block
#define NCHUNK    8       // chunks of 512 channels
#define CHUNK_F4  128     // float4 per token per chunk
#define BUF_F4    1024    // float4 per buffer (T * CHUNK_F4)
#define BUF_BYTES 16384

// smem layout (bytes)
#define SMEM_SX    0          // 2 x [8 tok][512 ch] floats      32768
#define SMEM_PART  32768      // float part[8][8][32]             8192
#define SMEM_SSQR  40960      // float ssqr[8]                      32
#define SMEM_DOTS  40992      // float dots[8][24]                 768
#define SMEM_SG    41760      // float sG[8][16]                   512
#define SMEM_TOTAL 42272

__device__ __forceinline__ void load_chunk(uint32_t sbase, const float4* x4g,
                                           size_t tok0, int cc, int tid) {
    const int buf = cc & 1;
    const uint32_t dst0 = sbase + buf * BUF_BYTES + tid * 16;
#pragma unroll
    for (int i = 0; i < 4; i++) {
        int idx = i * 256 + tid;        // == t*128 + c4
        int t   = idx >> 7;
        int c4  = idx & 127;
        // token stride: 1024 float4 (4096 floats); chunk cc covers
        // float4 [cc*128, cc*128+128) of the token
        const float4* src = x4g + ((tok0 + t) * 1024 + cc * CHUNK_F4 + c4);
        asm volatile("cp.async.cg.shared.global [%0], [%1], 16;"
                     :: "r"(dst0 + i * 4096), "l"(src));
    }
    asm volatile("cp.async.commit_group;");
}

__global__ void __launch_bounds__(256, 3)
mhc_main_kernel(const float* __restrict__ x,
                const float* __restrict__ b_pre,
                const float* __restrict__ b_post,
                const float* __restrict__ b_res,
                float* __restrict__ out) {
    extern __shared__ char smem[];
    const float4*     sx4  = (const float4*)(smem + SMEM_SX);
    const ulonglong2* sxu  = (const ulonglong2*)(smem + SMEM_SX);
    float*            part = (float*)(smem + SMEM_PART);
    float*            ssqr = (float*)(smem + SMEM_SSQR);
    float*            dots = (float*)(smem + SMEM_DOTS);
    float*            sG   = (float*)(smem + SMEM_SG);

    const int tid  = threadIdx.x;
    const int g    = tid >> 5;   // warp id 0..7 (j-subslice; also ssq token)
    const int lane = tid & 31;   // weight row k (0..23 used)
    const size_t tok0 = (size_t)blockIdx.x * T;

    const float4*     x4g = (const float4*)x;
    const ulonglong2* xg2 = (const ulonglong2*)x;
    const ulonglong2* wq2 = (const ulonglong2*)g_Wq;

    const uint32_t sbase = (uint32_t)__cvta_generic_to_shared(smem);

    u64 acc[T];
#pragma unroll
    for (int t = 0; t < T; t++) acc[t] = 0ull;
    float ssql = 0.0f;  // warp g accumulates token g's ssq (lane-strided)

    // ------------------ Phase 1: double-buffered chunk loop -----------------
    load_chunk(sbase, x4g, tok0, 0, tid);

    for (int cc = 0; cc < NCHUNK; cc++) {
        if (cc < NCHUNK - 1) {
            load_chunk(sbase, x4g, tok0, cc + 1, tid);
            asm volatile("cp.async.wait_group 1;");
        } else {
            asm volatile("cp.async.wait_group 0;");
        }
        __syncthreads();

        const int buf = cc & 1;

        // ssq pass: warp g handles token g; lanes stride the 128 float4
        {
            const float4* sb = sx4 + buf * BUF_F4 + g * CHUNK_F4;
#pragma unroll
            for (int i = 0; i < 4; i++) {
                float4 v = sb[lane + i * 32];
                ssql = fmaf(v.x, v.x, ssql);
                ssql = fmaf(v.y, v.y, ssql);
                ssql = fmaf(v.z, v.z, ssql);
                ssql = fmaf(v.w, v.w, ssql);
            }
        }

        // dot pass: warp g covers j4 in [cc*128 + g*16, +16), all 8 tokens
        {
            const ulonglong2* xb = sxu + buf * BUF_F4;  // 1024 ul2 per buf
            const int bj = cc * 128 + g * 16;
#pragma unroll
            for (int m = 0; m < 16; m++) {
                ulonglong2 w = wq2[(size_t)(bj + m) * 32 + lane];
                const int jl = g * 16 + m;
#pragma unroll
                for (int t = 0; t < T; t++) {
                    ulonglong2 xv = xb[t * 128 + jl];  // LDS.128 broadcast
                    acc[t] = fma2(w.x, xv.x, acc[t]);
                    acc[t] = fma2(w.y, xv.y, acc[t]);
                }
            }
        }
        __syncthreads();  // all reads of this buffer done before reuse
    }

    // ------------------ Phase 2: reductions, sigmoids, Cayley, fold ---------
#pragma unroll
    for (int t = 0; t < T; t++) {
        float lo, hi;
        upk2(acc[t], lo, hi);
        part[(g * T + t) * 32 + lane] = lo + hi;  // part[g][t][k]
    }
    // ssq: full-warp reduce, lane 0 writes token g's total
    ssql += __shfl_xor_sync(0xffffffffu, ssql, 16);
    ssql += __shfl_xor_sync(0xffffffffu, ssql, 8);
    ssql += __shfl_xor_sync(0xffffffffu, ssql, 4);
    ssql += __shfl_xor_sync(0xffffffffu, ssql, 2);
    ssql += __shfl_xor_sync(0xffffffffu, ssql, 1);
    if (lane == 0) ssqr[g] = ssql;
    __syncthreads();

    for (int idx = tid; idx < T * 24; idx += 256) {
        int t = idx / 24;
        int k = idx - t * 24;
        float s = 0.0f;
#pragma unroll
        for (int gg = 0; gg < 8; gg++) s += part[(gg * T + t) * 32 + k];
        dots[t * 24 + k] = s;
    }
    __syncthreads();

    if (tid < T) {
        const int t = tid;
        float rinv = rsqrtf(ssqr[t] * (1.0f / 4096.0f) + 1e-6f);
        float d[24];
#pragma unroll
        for (int k = 0; k < 24; k++) d[k] = dots[t * 24 + k] * rinv;

        float Hpre[4], Hpost[4];
#pragma unroll
        for (int i = 0; i < 4; i++) {
            Hpre[i]  = 1.0f / (1.0f + expf(-(d[i]     + b_pre[i])));
            Hpost[i] = 2.0f / (1.0f + expf(-(d[4 + i] + b_post[i])));
        }
        // Cayley: A = I - S, Bq = I + S, S = 0.5 (M - M^T)
        float A[4][4], Bq[4][4];
#pragma unroll
        for (int a = 0; a < 4; a++)
#pragma unroll
            for (int b = 0; b < 4; b++) {
                float Mab = d[8 + a * 4 + b] + b_res[a * 4 + b];
                float Mba = d[8 + b * 4 + a] + b_res[b * 4 + a];
                float S   = 0.5f * (Mab - Mba);
                float id  = (a == b) ? 1.0f : 0.0f;
                A[a][b]  = id - S;
                Bq[a][b] = id + S;
            }
#pragma unroll
        for (int r = 0; r < 4; r++) {
            float inv = 1.0f / A[r][r];
#pragma unroll
            for (int c = 0; c < 4; c++) { A[r][c] *= inv; Bq[r][c] *= inv; }
#pragma unroll
            for (int rr = 0; rr < 4; rr++) {
                if (rr == r) continue;
                float f = A[rr][r];
#pragma unroll
                for (int c = 0; c < 4; c++) {
                    A[rr][c]  -= f * A[r][c];
                    Bq[rr][c] -= f * Bq[r][c];
                }
            }
        }
#pragma unroll
        for (int m = 0; m < 4; m++)
#pragma unroll
            for (int n = 0; n < 4; n++)
                sG[t * 16 + m * 4 + n] = Bq[m][n] + Hpost[m] * Hpre[n];
    }
    __syncthreads();

    // ------------------ Phase 3: out = G @ x (per token, L2-hot x) ----------
    ulonglong2* og2 = (ulonglong2*)out;
    for (int it = 0; it < T; it++) {
        u64 g2a[16];
#pragma unroll
        for (int q = 0; q < 16; q++) {
            float gv = sG[it * 16 + q];
            g2a[q] = pk2(gv, gv);
        }
        u64 xl[4], xh[4];
#pragma unroll
        for (int n = 0; n < 4; n++) {
            ulonglong2 v = xg2[(tok0 + it) * 1024 + n * 256 + tid];
            xl[n] = v.x;
            xh[n] = v.y;
        }
#pragma unroll
        for (int m = 0; m < 4; m++) {
            u64 al = 0ull, ah = 0ull;
#pragma unroll
            for (int n = 0; n < 4; n++) {
                al = fma2(g2a[m * 4 + n], xl[n], al);
                ah = fma2(g2a[m * 4 + n], xh[n], ah);
            }
            ulonglong2 o;
            o.x = al;
            o.y = ah;
            og2[(tok0 + it) * 1024 + m * 256 + tid] = o;
        }
    }
}

extern "C" void kernel_launch(void* const* d_in, const int* in_sizes, int n_in,
                              void* d_out, int out_size) {
    const float* x      = (const float*)d_in[0];
    const float* norm_w = (const float*)d_in[1];
    const float* W_pre  = (const float*)d_in[2];
    const float* W_post = (const float*)d_in[3];
    const float* W_res  = (const float*)d_in[4];
    const float* b_pre  = (const float*)d_in[5];
    const float* b_post = (const float*)d_in[6];
    const float* b_res  = (const float*)d_in[7];
    const float* a_pre  = (const float*)d_in[8];
    const float* a_post = (const float*)d_in[9];
    const float* a_res  = (const float*)d_in[10];
    float* out = (float*)d_out;

    const int BL   = in_sizes[0] / 4096;  // 16384 tokens
    const int nblk = BL / T;              // 2048 blocks

    cudaFuncSetAttribute(mhc_main_kernel,
                         cudaFuncAttributeMaxDynamicSharedMemorySize,
                         SMEM_TOTAL);

    mhc_prep_kernel<<<512, 256>>>(norm_w, W_pre, W_post, W_res,
                                  a_pre, a_post, a_res);
    mhc_main_kernel<<<nblk, 256, SMEM_TOTAL>>>(x, b_pre, b_post, b_res, out);
}